// round 3
// baseline (speedup 1.0000x reference)
#include <cuda_runtime.h>
#include <cstdint>

// ---------------- problem constants ----------------
#define HID 64
#define INDIM 4800
#define DEPTH 14
#define NNODES 16383          // 2^14 - 1
#define NGEMM 256             // 4*HID

// ---------------- scratch ----------------
__device__ float g_Wx[NNODES * NGEMM];
__device__ float g_h[NNODES * HID];
__device__ float g_c[NNODES * HID];
__device__ float g_Uit[HID * HID];
__device__ float g_Uft[HID * HID];
__device__ float g_Uot[HID * HID];
__device__ float g_Uut[HID * HID];
__device__ float g_convWt[2 * HID * HID];
__device__ float g_v[3 * HID];

// ---------------- helpers ----------------
__device__ __forceinline__ float sigmoidf_(float x) { return 1.f / (1.f + __expf(-x)); }

__device__ __forceinline__ float rna_tf32(float x) {
    unsigned r;
    asm("cvt.rna.tf32.f32 %0, %1;" : "=r"(r) : "f"(x));
    return __uint_as_float(r);
}

__device__ __forceinline__ void mma_tf32(float* d, const unsigned* a, const unsigned* b) {
    asm volatile(
        "mma.sync.aligned.m16n8k8.row.col.f32.tf32.tf32.f32 "
        "{%0,%1,%2,%3},{%4,%5,%6,%7},{%8,%9},{%0,%1,%2,%3};"
        : "+f"(d[0]), "+f"(d[1]), "+f"(d[2]), "+f"(d[3])
        : "r"(a[0]), "r"(a[1]), "r"(a[2]), "r"(a[3]), "r"(b[0]), "r"(b[1]));
}

__device__ __forceinline__ void cp_async16(float* smem_dst, const float* gsrc) {
    unsigned sa = (unsigned)__cvta_generic_to_shared(smem_dst);
    asm volatile("cp.async.cg.shared.global [%0], [%1], 16;\n" :: "r"(sa), "l"(gsrc));
}
__device__ __forceinline__ void cp_commit() { asm volatile("cp.async.commit_group;\n" ::: "memory"); }

// ---------------- GEMM config: 128x256 tile, full N per block ----------------
#define THREADS 512
#define BM 128
#define BN 256
#define BK 32
#define NK (INDIM / BK)       // 150
#define PADK 36               // BK + 4 -> conflict-free 32-bit frag LDS
#define AST (BM * PADK)       // 4608 floats
#define BST (BN * PADK)       // 9216 floats
#define STF (AST + BST)       // 13824 floats per stage
#define NSTG 3
#define SMEM_FLOATS (NSTG * STF + 256)
#define GEMM_SMEM (SMEM_FLOATS * 4)       // 166912 bytes

__global__ void __launch_bounds__(THREADS, 1)
gemm_tc(const float* __restrict__ A,      // [NNODES, INDIM]
        const float* __restrict__ B,      // [NGEMM, INDIM]
        const float* __restrict__ bias)   // [NGEMM]
{
    extern __shared__ float smem[];
    float* sbias = smem + NSTG * STF;

    const int tid  = threadIdx.x;
    const int lane = tid & 31;
    const int warp = tid >> 5;
    const int wm = warp >> 2;          // 0..3
    const int wn = warp & 3;           // 0..3
    const int m0 = wm * 32;
    const int n0 = wn * 64;
    const int bm = blockIdx.x * BM;

    if (tid < 256) sbias[tid] = bias[tid];

    float acc[2][8][4];
#pragma unroll
    for (int i = 0; i < 2; ++i)
#pragma unroll
        for (int j = 0; j < 8; ++j)
#pragma unroll
            for (int k = 0; k < 4; ++k) acc[i][j][k] = 0.f;

    auto issue = [&](int t) {
        float* stg = smem + (t % NSTG) * STF;
        const int k0 = t * BK;
#pragma unroll
        for (int i = 0; i < 6; ++i) {
            int idx = tid + i * THREADS;       // 0..3071
            if (idx < 1024) {                  // A: 128 rows x 8 float4
                int row = idx >> 3, c4 = idx & 7;
                int gr = bm + row; if (gr > NNODES - 1) gr = NNODES - 1;
                cp_async16(stg + row * PADK + c4 * 4,
                           A + (size_t)gr * INDIM + k0 + c4 * 4);
            } else {                           // B: 256 rows x 8 float4
                int cb = idx - 1024;
                int row = cb >> 3, c4 = cb & 7;
                cp_async16(stg + AST + row * PADK + c4 * 4,
                           B + (size_t)row * INDIM + k0 + c4 * 4);
            }
        }
        cp_commit();
    };

    issue(0); issue(1);

    for (int s = 0; s < NK; ++s) {
        if (s + 2 < NK) issue(s + 2); else cp_commit();
        asm volatile("cp.async.wait_group 2;" ::: "memory");
        __syncthreads();

        float* stg = smem + (s % NSTG) * STF;
        // one-shot RNA tf32 rounding of this stage
#pragma unroll
        for (int i = 0; i < 7; ++i) {
            int idx = tid + i * THREADS;
            if (idx < STF / 4) {
                float4* p = (float4*)stg + idx;
                float4 v = *p;
                v.x = rna_tf32(v.x); v.y = rna_tf32(v.y);
                v.z = rna_tf32(v.z); v.w = rna_tf32(v.w);
                *p = v;
            }
        }
        __syncthreads();

        const float* tA = stg;
        const float* tB = stg + AST;
        const int r  = lane >> 2;
        const int cc = lane & 3;

#pragma unroll
        for (int ks = 0; ks < 4; ++ks) {
            const int kcol = ks * 8;
            unsigned af[2][4], bf[8][2];
#pragma unroll
            for (int im = 0; im < 2; ++im) {
                const float* base = tA + (m0 + im * 16 + r) * PADK + kcol + cc;
                af[im][0] = __float_as_uint(base[0]);
                af[im][1] = __float_as_uint(base[8 * PADK]);
                af[im][2] = __float_as_uint(base[4]);
                af[im][3] = __float_as_uint(base[8 * PADK + 4]);
            }
#pragma unroll
            for (int in = 0; in < 8; ++in) {
                const float* bb = tB + (n0 + in * 8 + r) * PADK + kcol + cc;
                bf[in][0] = __float_as_uint(bb[0]);
                bf[in][1] = __float_as_uint(bb[4]);
            }
#pragma unroll
            for (int im = 0; im < 2; ++im)
#pragma unroll
                for (int in = 0; in < 8; ++in)
                    mma_tf32(acc[im][in], af[im], bf[in]);
        }
        __syncthreads();
    }

    // epilogue: bias + store
#pragma unroll
    for (int im = 0; im < 2; ++im) {
#pragma unroll
        for (int in = 0; in < 8; ++in) {
            int rr = bm + m0 + im * 16 + (lane >> 2);
            int cg = n0 + in * 8 + (lane & 3) * 2;
            float b0 = sbias[cg], b1 = sbias[cg + 1];
            if (rr < NNODES) {
                float2 v = make_float2(acc[im][in][0] + b0, acc[im][in][1] + b1);
                *(float2*)(g_Wx + (size_t)rr * NGEMM + cg) = v;
            }
            int rr2 = rr + 8;
            if (rr2 < NNODES) {
                float2 v = make_float2(acc[im][in][2] + b0, acc[im][in][3] + b1);
                *(float2*)(g_Wx + (size_t)rr2 * NGEMM + cg) = v;
            }
        }
    }
}

// ---------------- prep: transpose weights, leaf constants ----------------
__global__ void prep_kernel(const float* __restrict__ U_i, const float* __restrict__ U_f,
                            const float* __restrict__ U_o, const float* __restrict__ U_u,
                            const float* __restrict__ convW, const float* __restrict__ conv_b)
{
    int t = threadIdx.x;
    for (int idx = t; idx < HID * HID; idx += 256) {
        int o = idx >> 6, h = idx & 63;
        g_Uit[h * HID + o] = U_i[idx];
        g_Uft[h * HID + o] = U_f[idx];
        g_Uot[h * HID + o] = U_o[idx];
        g_Uut[h * HID + o] = U_u[idx];
    }
    for (int idx = t; idx < 2 * HID * HID; idx += 256) {
        int o = idx >> 7, kh = idx & 127;
        g_convWt[kh * HID + o] = convW[idx];
    }
    if (t < HID) {
        float vi = 0.f, vo = 0.f, vu = 0.f;
        for (int h = 0; h < HID; ++h) {
            float b = conv_b[h];
            vi += b * U_i[t * HID + h];
            vo += b * U_o[t * HID + h];
            vu += b * U_u[t * HID + h];
        }
        g_v[t] = vi; g_v[HID + t] = vo; g_v[2 * HID + t] = vu;
    }
}

// ---------------- leaves ----------------
__global__ void leaf_kernel()
{
    int idx = blockIdx.x * blockDim.x + threadIdx.x;
    int o = idx & 63;
    int node = (1 << (DEPTH - 1)) - 1 + (idx >> 6);
    const float* wx = g_Wx + (size_t)node * NGEMM;
    float zi = wx[o]       + g_v[o];
    float zo = wx[128 + o] + g_v[HID + o];
    float zu = wx[192 + o] + g_v[2 * HID + o];
    float iv = sigmoidf_(zi);
    float ov = sigmoidf_(zo);
    float uv = tanhf(zu);
    float c  = iv * uv;
    g_c[(size_t)node * HID + o] = c;
    g_h[(size_t)node * HID + o] = ov * tanhf(c);
}

// ---------------- inner levels: 16 nodes/block, 4 nodes/thread ----------
__device__ __forceinline__ void level16(int start, int n, int jb, int g, int o,
                                        float (*sh)[128], float (*sc)[128], float (*sa)[64],
                                        float convb_o)
{
    int node[4]; bool ok[4];
#pragma unroll
    for (int t = 0; t < 4; ++t) {
        int l = g + 4 * t;
        int j = jb + l;
        ok[t] = j < n;
        node[t] = start + j;
        if (ok[t]) {
            int base = (2 * node[t] + 1) * HID;
            sh[l][o]      = g_h[base + o];
            sh[l][64 + o] = g_h[base + 64 + o];
            sc[l][o]      = g_c[base + o];
            sc[l][64 + o] = g_c[base + 64 + o];
        }
    }
    __syncthreads();

    float avg[4], f0[4], f1[4];
#pragma unroll
    for (int t = 0; t < 4; ++t) {
        avg[t] = convb_o;
        f0[t] = ok[t] ? g_Wx[(size_t)node[t] * NGEMM + 64 + o] : 0.f;
        f1[t] = f0[t];
    }
#pragma unroll 4
    for (int h = 0; h < 128; ++h) {
        float w = g_convWt[h * HID + o];
#pragma unroll
        for (int t = 0; t < 4; ++t) avg[t] += sh[g + 4 * t][h] * w;
    }
#pragma unroll 4
    for (int h = 0; h < HID; ++h) {
        float w = g_Uft[h * HID + o];
#pragma unroll
        for (int t = 0; t < 4; ++t) {
            f0[t] += sh[g + 4 * t][h] * w;
            f1[t] += sh[g + 4 * t][64 + h] * w;
        }
    }
    float sumf[4];
#pragma unroll
    for (int t = 0; t < 4; ++t) {
        int l = g + 4 * t;
        sumf[t] = sigmoidf_(f0[t]) * sc[l][o] + sigmoidf_(f1[t]) * sc[l][64 + o];
        sa[l][o] = avg[t];
    }
    __syncthreads();

    float zi[4], zo[4], zu[4];
#pragma unroll
    for (int t = 0; t < 4; ++t) {
        if (ok[t]) {
            const float* wx = g_Wx + (size_t)node[t] * NGEMM;
            zi[t] = wx[o]; zo[t] = wx[128 + o]; zu[t] = wx[192 + o];
        } else { zi[t] = zo[t] = zu[t] = 0.f; }
    }
#pragma unroll 4
    for (int h = 0; h < HID; ++h) {
        float wi = g_Uit[h * HID + o];
        float wo = g_Uot[h * HID + o];
        float wu = g_Uut[h * HID + o];
#pragma unroll
        for (int t = 0; t < 4; ++t) {
            float a = sa[g + 4 * t][h];
            zi[t] += a * wi; zo[t] += a * wo; zu[t] += a * wu;
        }
    }
#pragma unroll
    for (int t = 0; t < 4; ++t) {
        if (ok[t]) {
            float c = sumf[t] + sigmoidf_(zi[t]) * tanhf(zu[t]);
            g_c[(size_t)node[t] * HID + o] = c;
            g_h[(size_t)node[t] * HID + o] = sigmoidf_(zo[t]) * tanhf(c);
        }
    }
    __syncthreads();
}

__global__ void __launch_bounds__(256)
level_kernel(const float* __restrict__ conv_b, int start, int n)
{
    __shared__ float sh[16][128], sc[16][128], sa[16][64];
    int g = threadIdx.x >> 6, o = threadIdx.x & 63;
    level16(start, n, blockIdx.x * 16, g, o, sh, sc, sa, conv_b[o]);
}

__global__ void __launch_bounds__(256)
top_kernel(const float* __restrict__ conv_b, float* __restrict__ out)
{
    __shared__ float sh[16][128], sc[16][128], sa[16][64];
    int g = threadIdx.x >> 6, o = threadIdx.x & 63;
    float cb = conv_b[o];
    for (int d = 5; d >= 0; --d) {
        int n = 1 << d, start = n - 1;
        for (int jb = 0; jb < n; jb += 16)
            level16(start, n, jb, g, o, sh, sc, sa, cb);
    }
    if (threadIdx.x < HID) {
        out[threadIdx.x]       = g_h[threadIdx.x];
        out[HID + threadIdx.x] = g_c[threadIdx.x];
    }
}

// ---------------- launch ----------------
extern "C" void kernel_launch(void* const* d_in, const int* in_sizes, int n_in,
                              void* d_out, int out_size)
{
    const float* inputs = (const float*)d_in[0];
    const float* Wx_w   = (const float*)d_in[1];
    const float* Wx_b   = (const float*)d_in[2];
    const float* U_i    = (const float*)d_in[3];
    const float* U_f    = (const float*)d_in[4];
    const float* U_o    = (const float*)d_in[5];
    const float* U_u    = (const float*)d_in[6];
    const float* convW  = (const float*)d_in[7];
    const float* conv_b = (const float*)d_in[8];
    float* out = (float*)d_out;

    cudaFuncSetAttribute(gemm_tc, cudaFuncAttributeMaxDynamicSharedMemorySize, GEMM_SMEM);

    prep_kernel<<<1, 256>>>(U_i, U_f, U_o, U_u, convW, conv_b);
    gemm_tc<<<(NNODES + BM - 1) / BM, THREADS, GEMM_SMEM>>>(inputs, Wx_w, Wx_b);
    leaf_kernel<<<(1 << (DEPTH - 1)) * HID / 256, 256>>>();
    for (int d = DEPTH - 2; d >= 6; --d) {
        int n = 1 << d;
        level_kernel<<<(n + 15) / 16, 256>>>(conv_b, n - 1, n);
    }
    top_kernel<<<1, 256>>>(conv_b, out);
}

// round 4
// speedup vs baseline: 1.0560x; 1.0560x over previous
#include <cuda_runtime.h>
#include <cstdint>

// ---------------- problem constants ----------------
#define HID 64
#define INDIM 4800
#define DEPTH 14
#define NNODES 16383          // 2^14 - 1
#define NGEMM 256             // 4*HID
#define NLEAF 8192

// ---------------- scratch ----------------
__device__ float g_Wx[NNODES * NGEMM];
__device__ float g_Br[NGEMM * INDIM];      // RNA-rounded copy of Wx_w
__device__ float g_h[NNODES * HID];
__device__ float g_c[NNODES * HID];
__device__ float g_Uit[HID * HID];         // [h][o]
__device__ float g_Uft[HID * HID];
__device__ float g_Uot[HID * HID];
__device__ float g_Uut[HID * HID];
__device__ float g_convWt[2 * HID * HID];  // [kh][o]
__device__ float g_v[3 * HID];             // conv_b @ U_{i,o,u}.T
__device__ unsigned g_bar[16];

// ---------------- helpers ----------------
__device__ __forceinline__ float sigmoidf_(float x) { return 1.f / (1.f + __expf(-x)); }

__device__ __forceinline__ float rna_tf32(float x) {
    unsigned r;
    asm("cvt.rna.tf32.f32 %0, %1;" : "=r"(r) : "f"(x));
    return __uint_as_float(r);
}
__device__ __forceinline__ unsigned f2tf32(float x) {
    unsigned r;
    asm("cvt.rna.tf32.f32 %0, %1;" : "=r"(r) : "f"(x));
    return r;
}

__device__ __forceinline__ void mma_tf32(float* d, const unsigned* a, const unsigned* b) {
    asm volatile(
        "mma.sync.aligned.m16n8k8.row.col.f32.tf32.tf32.f32 "
        "{%0,%1,%2,%3},{%4,%5,%6,%7},{%8,%9},{%0,%1,%2,%3};"
        : "+f"(d[0]), "+f"(d[1]), "+f"(d[2]), "+f"(d[3])
        : "r"(a[0]), "r"(a[1]), "r"(a[2]), "r"(a[3]), "r"(b[0]), "r"(b[1]));
}

__device__ __forceinline__ void cp_async16(float* smem_dst, const float* gsrc) {
    unsigned sa = (unsigned)__cvta_generic_to_shared(smem_dst);
    asm volatile("cp.async.cg.shared.global [%0], [%1], 16;\n" :: "r"(sa), "l"(gsrc));
}
__device__ __forceinline__ void cp_commit() { asm volatile("cp.async.commit_group;\n" ::: "memory"); }

// ---------------- prep: round B, transpose weights, leaf consts, zero bar ---
__global__ void prep_kernel(const float* __restrict__ Wx_w,
                            const float* __restrict__ U_i, const float* __restrict__ U_f,
                            const float* __restrict__ U_o, const float* __restrict__ U_u,
                            const float* __restrict__ convW, const float* __restrict__ conv_b)
{
    const int nt = gridDim.x * blockDim.x;
    const int t0 = blockIdx.x * blockDim.x + threadIdx.x;
    // RNA-round B into g_Br
    for (int i = t0; i < NGEMM * INDIM / 4; i += nt) {
        float4 v = ((const float4*)Wx_w)[i];
        v.x = rna_tf32(v.x); v.y = rna_tf32(v.y);
        v.z = rna_tf32(v.z); v.w = rna_tf32(v.w);
        ((float4*)g_Br)[i] = v;
    }
    if (blockIdx.x == 0) {
        int t = threadIdx.x;
        for (int idx = t; idx < HID * HID; idx += 256) {
            int o = idx >> 6, h = idx & 63;
            g_Uit[h * HID + o] = U_i[idx];
            g_Uft[h * HID + o] = U_f[idx];
            g_Uot[h * HID + o] = U_o[idx];
            g_Uut[h * HID + o] = U_u[idx];
        }
        for (int idx = t; idx < 2 * HID * HID; idx += 256) {
            int o = idx >> 7, kh = idx & 127;
            g_convWt[kh * HID + o] = convW[idx];
        }
        if (t < HID) {
            float vi = 0.f, vo = 0.f, vu = 0.f;
            for (int h = 0; h < HID; ++h) {
                float b = conv_b[h];
                vi += b * U_i[t * HID + h];
                vo += b * U_o[t * HID + h];
                vu += b * U_u[t * HID + h];
            }
            g_v[t] = vi; g_v[HID + t] = vo; g_v[2 * HID + t] = vu;
        }
        if (t < 16) g_bar[t] = 0;
    }
}

// ---------------- GEMM: 128x128 tile, 3-stage, B pre-rounded ----------------
#define BM 128
#define BN 128
#define BK 32
#define NK (INDIM / BK)       // 150
#define PADK 36
#define AST (BM * PADK)       // 4608 floats
#define STF (2 * AST)         // A + B per stage
#define NSTG 3
#define GEMM_SMEM (NSTG * STF * 4)   // 110592 bytes

__global__ void __launch_bounds__(256, 2)
gemm_kernel(const float* __restrict__ A, const float* __restrict__ bias)
{
    extern __shared__ float smem[];
    const int tid  = threadIdx.x;
    const int lane = tid & 31;
    const int warp = tid >> 5;
    const int wm = warp >> 1;          // 0..3
    const int wn = warp & 1;           // 0..1
    const int m0 = wm * 32;
    const int n0 = wn * 64;
    const int bm = blockIdx.y * BM;
    const int bn = blockIdx.x * BN;

    float acc[2][8][4];
#pragma unroll
    for (int i = 0; i < 2; ++i)
#pragma unroll
        for (int j = 0; j < 8; ++j)
#pragma unroll
            for (int k = 0; k < 4; ++k) acc[i][j][k] = 0.f;

    auto issue = [&](int t) {
        float* stg = smem + (t % NSTG) * STF;
        const int k0 = t * BK;
#pragma unroll
        for (int i = 0; i < 4; ++i) {
            int idx = tid + i * 256;          // 0..1023
            int row = idx >> 3, c4 = idx & 7;
            int gr = bm + row; if (gr > NNODES - 1) gr = NNODES - 1;
            cp_async16(stg + row * PADK + c4 * 4,
                       A + (size_t)gr * INDIM + k0 + c4 * 4);
            cp_async16(stg + AST + row * PADK + c4 * 4,
                       g_Br + (size_t)(bn + row) * INDIM + k0 + c4 * 4);
        }
        cp_commit();
    };

    issue(0); issue(1);

    for (int s = 0; s < NK; ++s) {
        if (s + 2 < NK) issue(s + 2); else cp_commit();
        asm volatile("cp.async.wait_group 2;" ::: "memory");
        __syncthreads();

        const float* tA = smem + (s % NSTG) * STF;
        const float* tB = tA + AST;
        const int r  = lane >> 2;
        const int cc = lane & 3;

#pragma unroll
        for (int ks = 0; ks < 4; ++ks) {
            const int kcol = ks * 8;
            unsigned af[2][4], bf[8][2];
#pragma unroll
            for (int im = 0; im < 2; ++im) {
                const float* base = tA + (m0 + im * 16 + r) * PADK + kcol + cc;
                af[im][0] = f2tf32(base[0]);
                af[im][1] = f2tf32(base[8 * PADK]);
                af[im][2] = f2tf32(base[4]);
                af[im][3] = f2tf32(base[8 * PADK + 4]);
            }
#pragma unroll
            for (int in = 0; in < 8; ++in) {
                const float* bb = tB + (n0 + in * 8 + r) * PADK + kcol + cc;
                bf[in][0] = __float_as_uint(bb[0]);
                bf[in][1] = __float_as_uint(bb[4]);
            }
#pragma unroll
            for (int im = 0; im < 2; ++im)
#pragma unroll
                for (int in = 0; in < 8; ++in)
                    mma_tf32(acc[im][in], af[im], bf[in]);
        }
        __syncthreads();
    }

#pragma unroll
    for (int im = 0; im < 2; ++im) {
#pragma unroll
        for (int in = 0; in < 8; ++in) {
            int rr = bm + m0 + im * 16 + (lane >> 2);
            int cg = bn + n0 + in * 8 + (lane & 3) * 2;
            float b0 = bias[cg], b1 = bias[cg + 1];
            if (rr < NNODES) {
                float2 v = make_float2(acc[im][in][0] + b0, acc[im][in][1] + b1);
                *(float2*)(g_Wx + (size_t)rr * NGEMM + cg) = v;
            }
            int rr2 = rr + 8;
            if (rr2 < NNODES) {
                float2 v = make_float2(acc[im][in][2] + b0, acc[im][in][3] + b1);
                *(float2*)(g_Wx + (size_t)rr2 * NGEMM + cg) = v;
            }
        }
    }
}

// ---------------- persistent tree kernel ----------------
#define TGRID 148
#define TTHREADS 256
#define TW (TGRID * 8)

__device__ __forceinline__ void gridbar(int i) {
    __syncthreads();
    if (threadIdx.x == 0) {
        __threadfence();
        unsigned prev = atomicAdd(&g_bar[i], 1u);
        if (prev + 1u < (unsigned)TGRID) {
            while (*(volatile unsigned*)&g_bar[i] < (unsigned)TGRID) { __nanosleep(64); }
        }
        __threadfence();
    }
    __syncthreads();
}

__global__ void __launch_bounds__(TTHREADS, 1)
tree_kernel(const float* __restrict__ conv_b, float* __restrict__ out)
{
    __shared__ float SH[8][256], SC[8][256], SA[8][128];
    const int tid = threadIdx.x, lane = tid & 31, warp = tid >> 5;
    const int gw = blockIdx.x * 8 + warp;
    float* shw = SH[warp];
    float* scw = SC[warp];
    float* saw = SA[warp];
    const float cb0 = conv_b[lane], cb1 = conv_b[lane + 32];

    // ---- leaves ----
    for (int idx = blockIdx.x * TTHREADS + tid; idx < NLEAF * HID; idx += TGRID * TTHREADS) {
        int node = (NLEAF - 1) + (idx >> 6);
        int o = idx & 63;
        const float* wx = g_Wx + (size_t)node * NGEMM;
        float zi = wx[o]       + g_v[o];
        float zo = wx[128 + o] + g_v[64 + o];
        float zu = wx[192 + o] + g_v[128 + o];
        float c = sigmoidf_(zi) * tanhf(zu);
        g_c[(size_t)node * HID + o] = c;
        g_h[(size_t)node * HID + o] = sigmoidf_(zo) * tanhf(c);
    }
    int bi = 0;
    gridbar(bi++);

    // ---- inner levels d = 12..0, one warp per node-pair ----
    for (int d = DEPTH - 2; d >= 0; --d) {
        const int n = 1 << d, start = n - 1;
        for (int j = gw * 2; j < n; j += TW * 2) {
            const int nd0 = start + j;
            const bool two = (j + 1 < n);
            const int nd1 = nd0 + (two ? 1 : 0);

            // load children (contiguous 128 floats per node)
            ((float4*)shw)[lane]         = ((const float4*)(g_h + (size_t)(2 * nd0 + 1) * HID))[lane];
            ((float4*)(shw + 128))[lane] = ((const float4*)(g_h + (size_t)(2 * nd1 + 1) * HID))[lane];
            ((float4*)scw)[lane]         = ((const float4*)(g_c + (size_t)(2 * nd0 + 1) * HID))[lane];
            ((float4*)(scw + 128))[lane] = ((const float4*)(g_c + (size_t)(2 * nd1 + 1) * HID))[lane];

            const float* wx0 = g_Wx + (size_t)nd0 * NGEMM;
            const float* wx1 = g_Wx + (size_t)nd1 * NGEMM;
            float xi00 = wx0[lane],       xi01 = wx0[lane + 32];
            float xi10 = wx1[lane],       xi11 = wx1[lane + 32];
            float xf00 = wx0[64 + lane],  xf01 = wx0[96 + lane];
            float xf10 = wx1[64 + lane],  xf11 = wx1[96 + lane];
            float xo00 = wx0[128 + lane], xo01 = wx0[160 + lane];
            float xo10 = wx1[128 + lane], xo11 = wx1[160 + lane];
            float xu00 = wx0[192 + lane], xu01 = wx0[224 + lane];
            float xu10 = wx1[192 + lane], xu11 = wx1[224 + lane];
            __syncwarp();

            // conv: avg over both children (kh flat = 128)
            float a00 = cb0, a01 = cb1, a10 = cb0, a11 = cb1;
#pragma unroll 4
            for (int h = 0; h < 128; ++h) {
                float w0 = g_convWt[h * 64 + lane], w1 = g_convWt[h * 64 + lane + 32];
                float s0 = shw[h], s1 = shw[128 + h];
                a00 += s0 * w0; a01 += s0 * w1; a10 += s1 * w0; a11 += s1 * w1;
            }
            saw[lane] = a00; saw[lane + 32] = a01;
            saw[64 + lane] = a10; saw[96 + lane] = a11;

            // forget gates per child
            float fl00 = xf00, fl01 = xf01, fl10 = xf10, fl11 = xf11;
            float fr00 = xf00, fr01 = xf01, fr10 = xf10, fr11 = xf11;
#pragma unroll 4
            for (int h = 0; h < 64; ++h) {
                float w0 = g_Uft[h * 64 + lane], w1 = g_Uft[h * 64 + lane + 32];
                float l0 = shw[h], r0 = shw[64 + h];
                float l1 = shw[128 + h], r1 = shw[192 + h];
                fl00 += l0 * w0; fl01 += l0 * w1; fl10 += l1 * w0; fl11 += l1 * w1;
                fr00 += r0 * w0; fr01 += r0 * w1; fr10 += r1 * w0; fr11 += r1 * w1;
            }
            float sf00 = sigmoidf_(fl00) * scw[lane]        + sigmoidf_(fr00) * scw[64 + lane];
            float sf01 = sigmoidf_(fl01) * scw[lane + 32]   + sigmoidf_(fr01) * scw[96 + lane];
            float sf10 = sigmoidf_(fl10) * scw[128 + lane]  + sigmoidf_(fr10) * scw[192 + lane];
            float sf11 = sigmoidf_(fl11) * scw[160 + lane]  + sigmoidf_(fr11) * scw[224 + lane];
            __syncwarp();

            // i,o,u gates from avg
            float zi00 = xi00, zi01 = xi01, zi10 = xi10, zi11 = xi11;
            float zo00 = xo00, zo01 = xo01, zo10 = xo10, zo11 = xo11;
            float zu00 = xu00, zu01 = xu01, zu10 = xu10, zu11 = xu11;
#pragma unroll 2
            for (int h = 0; h < 64; ++h) {
                float wi0 = g_Uit[h * 64 + lane], wi1 = g_Uit[h * 64 + lane + 32];
                float wo0 = g_Uot[h * 64 + lane], wo1 = g_Uot[h * 64 + lane + 32];
                float wu0 = g_Uut[h * 64 + lane], wu1 = g_Uut[h * 64 + lane + 32];
                float q0 = saw[h], q1 = saw[64 + h];
                zi00 += q0 * wi0; zi01 += q0 * wi1; zi10 += q1 * wi0; zi11 += q1 * wi1;
                zo00 += q0 * wo0; zo01 += q0 * wo1; zo10 += q1 * wo0; zo11 += q1 * wo1;
                zu00 += q0 * wu0; zu01 += q0 * wu1; zu10 += q1 * wu0; zu11 += q1 * wu1;
            }

            {
                float c0 = sf00 + sigmoidf_(zi00) * tanhf(zu00);
                float h0 = sigmoidf_(zo00) * tanhf(c0);
                g_c[(size_t)nd0 * HID + lane] = c0;
                g_h[(size_t)nd0 * HID + lane] = h0;
                float c1 = sf01 + sigmoidf_(zi01) * tanhf(zu01);
                float h1 = sigmoidf_(zo01) * tanhf(c1);
                g_c[(size_t)nd0 * HID + lane + 32] = c1;
                g_h[(size_t)nd0 * HID + lane + 32] = h1;
                if (nd0 == 0) {
                    out[lane] = h0;  out[lane + 32] = h1;
                    out[64 + lane] = c0; out[96 + lane] = c1;
                }
                if (two) {
                    float c2 = sf10 + sigmoidf_(zi10) * tanhf(zu10);
                    g_c[(size_t)nd1 * HID + lane] = c2;
                    g_h[(size_t)nd1 * HID + lane] = sigmoidf_(zo10) * tanhf(c2);
                    float c3 = sf11 + sigmoidf_(zi11) * tanhf(zu11);
                    g_c[(size_t)nd1 * HID + lane + 32] = c3;
                    g_h[(size_t)nd1 * HID + lane + 32] = sigmoidf_(zo11) * tanhf(c3);
                }
            }
            __syncwarp();
        }
        gridbar(bi++);
    }
}

// ---------------- launch ----------------
extern "C" void kernel_launch(void* const* d_in, const int* in_sizes, int n_in,
                              void* d_out, int out_size)
{
    const float* inputs = (const float*)d_in[0];
    const float* Wx_w   = (const float*)d_in[1];
    const float* Wx_b   = (const float*)d_in[2];
    const float* U_i    = (const float*)d_in[3];
    const float* U_f    = (const float*)d_in[4];
    const float* U_o    = (const float*)d_in[5];
    const float* U_u    = (const float*)d_in[6];
    const float* convW  = (const float*)d_in[7];
    const float* conv_b = (const float*)d_in[8];
    float* out = (float*)d_out;

    cudaFuncSetAttribute(gemm_kernel, cudaFuncAttributeMaxDynamicSharedMemorySize, GEMM_SMEM);

    prep_kernel<<<64, 256>>>(Wx_w, U_i, U_f, U_o, U_u, convW, conv_b);
    gemm_kernel<<<dim3(2, 128), 256, GEMM_SMEM>>>(inputs, Wx_b);
    tree_kernel<<<TGRID, TTHREADS>>>(conv_b, out);
}

// round 5
// speedup vs baseline: 1.2890x; 1.2206x over previous
#include <cuda_runtime.h>
#include <cstdint>

// ---------------- problem constants ----------------
#define HID 64
#define INDIM 4800
#define DEPTH 14
#define NNODES 16383          // 2^14 - 1
#define NGEMM 256             // 4*HID
#define NLEAF 8192

// ---------------- scratch ----------------
__device__ float g_Wx[NNODES * NGEMM];
__device__ float g_Br[NGEMM * INDIM];      // RNA-rounded copy of Wx_w
__device__ float g_h[NNODES * HID];
__device__ float g_c[NNODES * HID];
__device__ float g_Uit[HID * HID];         // [h][o]
__device__ float g_Uft[HID * HID];
__device__ float g_Uot[HID * HID];
__device__ float g_Uut[HID * HID];
__device__ float g_convWt[2 * HID * HID];  // [kh][o]
__device__ float g_v[3 * HID];             // conv_b @ U_{i,o,u}.T
__device__ unsigned g_bar[32];

// ---------------- helpers ----------------
__device__ __forceinline__ float sigmoidf_(float x) { return 1.f / (1.f + __expf(-x)); }

__device__ __forceinline__ float rna_tf32(float x) {
    unsigned r;
    asm("cvt.rna.tf32.f32 %0, %1;" : "=r"(r) : "f"(x));
    return __uint_as_float(r);
}
__device__ __forceinline__ unsigned f2tf32(float x) {
    unsigned r;
    asm("cvt.rna.tf32.f32 %0, %1;" : "=r"(r) : "f"(x));
    return r;
}

__device__ __forceinline__ void mma_tf32(float* d, const unsigned* a, const unsigned* b) {
    asm volatile(
        "mma.sync.aligned.m16n8k8.row.col.f32.tf32.tf32.f32 "
        "{%0,%1,%2,%3},{%4,%5,%6,%7},{%8,%9},{%0,%1,%2,%3};"
        : "+f"(d[0]), "+f"(d[1]), "+f"(d[2]), "+f"(d[3])
        : "r"(a[0]), "r"(a[1]), "r"(a[2]), "r"(a[3]), "r"(b[0]), "r"(b[1]));
}

__device__ __forceinline__ void cp_async16(float* smem_dst, const float* gsrc) {
    unsigned sa = (unsigned)__cvta_generic_to_shared(smem_dst);
    asm volatile("cp.async.cg.shared.global [%0], [%1], 16;\n" :: "r"(sa), "l"(gsrc));
}
__device__ __forceinline__ void cp_commit() { asm volatile("cp.async.commit_group;\n" ::: "memory"); }

// ---------------- prep (512 blocks): round B, transposes, leaf consts -------
__global__ void prep_kernel(const float* __restrict__ Wx_w,
                            const float* __restrict__ U_i, const float* __restrict__ U_f,
                            const float* __restrict__ U_o, const float* __restrict__ U_u,
                            const float* __restrict__ convW, const float* __restrict__ conv_b)
{
    const int nt = gridDim.x * blockDim.x;
    const int t0 = blockIdx.x * blockDim.x + threadIdx.x;
    for (int i = t0; i < NGEMM * INDIM / 4; i += nt) {
        float4 v = ((const float4*)Wx_w)[i];
        v.x = rna_tf32(v.x); v.y = rna_tf32(v.y);
        v.z = rna_tf32(v.z); v.w = rna_tf32(v.w);
        ((float4*)g_Br)[i] = v;
    }
    for (int idx = t0; idx < HID * HID; idx += nt) {
        int o = idx >> 6, h = idx & 63;
        g_Uit[h * HID + o] = U_i[idx];
        g_Uft[h * HID + o] = U_f[idx];
        g_Uot[h * HID + o] = U_o[idx];
        g_Uut[h * HID + o] = U_u[idx];
    }
    for (int idx = t0; idx < 2 * HID * HID; idx += nt) {
        int o = idx >> 7, kh = idx & 127;
        g_convWt[kh * HID + o] = convW[idx];
    }
    if (t0 < HID) {
        float vi = 0.f, vo = 0.f, vu = 0.f;
        for (int h = 0; h < HID; ++h) {
            float b = conv_b[h];
            vi += b * U_i[t0 * HID + h];
            vo += b * U_o[t0 * HID + h];
            vu += b * U_u[t0 * HID + h];
        }
        g_v[t0] = vi; g_v[HID + t0] = vo; g_v[2 * HID + t0] = vu;
    }
    if (t0 < 32) g_bar[t0] = 0;
}

// ---------------- GEMM: 128x256 tile, 512 thr, 2-stage, 1 sync/k-tile ------
#define THREADS 512
#define BM 128
#define BN 256
#define BK 32
#define NK (INDIM / BK)       // 150
#define PADK 36
#define AST (BM * PADK)       // 4608 floats
#define BST (BN * PADK)       // 9216 floats
#define STF (AST + BST)       // 13824 floats
#define NSTG 2
#define GEMM_SMEM (NSTG * STF * 4)   // 110592 bytes

__global__ void __launch_bounds__(THREADS, 1)
gemm_kernel(const float* __restrict__ A, const float* __restrict__ bias)
{
    extern __shared__ float smem[];
    const int tid  = threadIdx.x;
    const int lane = tid & 31;
    const int warp = tid >> 5;
    const int m0 = (warp >> 2) * 32;   // 4 m-warps
    const int n0 = (warp & 3) * 64;    // 4 n-warps
    const int bm = blockIdx.x * BM;

    float acc[2][8][4];
#pragma unroll
    for (int i = 0; i < 2; ++i)
#pragma unroll
        for (int j = 0; j < 8; ++j)
#pragma unroll
            for (int k = 0; k < 4; ++k) acc[i][j][k] = 0.f;

    auto issue = [&](int t) {
        float* stg = smem + (t & 1) * STF;
        const int k0 = t * BK;
#pragma unroll
        for (int i = 0; i < 6; ++i) {
            int idx = tid + i * THREADS;          // 0..3071
            if (idx < 1024) {                     // A: 128 rows x 8 float4
                int row = idx >> 3, c4 = idx & 7;
                int gr = bm + row; if (gr > NNODES - 1) gr = NNODES - 1;
                cp_async16(stg + row * PADK + c4 * 4,
                           A + (size_t)gr * INDIM + k0 + c4 * 4);
            } else {                              // B: 256 rows x 8 float4
                int cb = idx - 1024;
                int row = cb >> 3, c4 = cb & 7;
                cp_async16(stg + AST + row * PADK + c4 * 4,
                           g_Br + (size_t)row * INDIM + k0 + c4 * 4);
            }
        }
        cp_commit();
    };

    issue(0);

    for (int s = 0; s < NK; ++s) {
        asm volatile("cp.async.wait_group 0;" ::: "memory");
        __syncthreads();
        if (s + 1 < NK) issue(s + 1);   // overlaps the whole MMA phase below

        const float* tA = smem + (s & 1) * STF;
        const float* tB = tA + AST;
        const int r  = lane >> 2;
        const int cc = lane & 3;

#pragma unroll
        for (int ks = 0; ks < 4; ++ks) {
            const int kcol = ks * 8;
            unsigned af[2][4], bf[8][2];
#pragma unroll
            for (int im = 0; im < 2; ++im) {
                const float* base = tA + (m0 + im * 16 + r) * PADK + kcol + cc;
                af[im][0] = f2tf32(base[0]);
                af[im][1] = f2tf32(base[8 * PADK]);
                af[im][2] = f2tf32(base[4]);
                af[im][3] = f2tf32(base[8 * PADK + 4]);
            }
#pragma unroll
            for (int in = 0; in < 8; ++in) {
                const float* bb = tB + (n0 + in * 8 + r) * PADK + kcol + cc;
                bf[in][0] = __float_as_uint(bb[0]);
                bf[in][1] = __float_as_uint(bb[4]);
            }
#pragma unroll
            for (int im = 0; im < 2; ++im)
#pragma unroll
                for (int in = 0; in < 8; ++in)
                    mma_tf32(acc[im][in], af[im], bf[in]);
        }
        // no trailing syncthreads: next iteration's sync guards stage reuse
    }

#pragma unroll
    for (int im = 0; im < 2; ++im) {
#pragma unroll
        for (int in = 0; in < 8; ++in) {
            int rr = bm + m0 + im * 16 + (lane >> 2);
            int cg = n0 + in * 8 + (lane & 3) * 2;
            float b0 = bias[cg], b1 = bias[cg + 1];
            if (rr < NNODES) {
                float2 v = make_float2(acc[im][in][0] + b0, acc[im][in][1] + b1);
                *(float2*)(g_Wx + (size_t)rr * NGEMM + cg) = v;
            }
            int rr2 = rr + 8;
            if (rr2 < NNODES) {
                float2 v = make_float2(acc[im][in][2] + b0, acc[im][in][3] + b1);
                *(float2*)(g_Wx + (size_t)rr2 * NGEMM + cg) = v;
            }
        }
    }
}

// ---------------- persistent tree kernel: 148 x 1024, weights in smem ------
#define TGRID 148
#define TTHREADS 1024
#define TWARPS 32
#define TW (TGRID * TWARPS)
// smem layout (floats): Uf 4096 | Ui 4096 | Uo 4096 | Uu 4096 | conv 8192 | 32*(256+256+128)
#define TS_UF 0
#define TS_UI 4096
#define TS_UO 8192
#define TS_UU 12288
#define TS_CV 16384
#define TS_WB 24576
#define TREE_SMEM ((TS_WB + TWARPS * 640) * 4)   // 180224 bytes

__device__ __forceinline__ void gridbar(int i) {
    __syncthreads();
    if (threadIdx.x == 0) {
        __threadfence();
        unsigned prev = atomicAdd(&g_bar[i], 1u);
        if (prev + 1u < (unsigned)TGRID) {
            while (*(volatile unsigned*)&g_bar[i] < (unsigned)TGRID) { __nanosleep(64); }
        }
        __threadfence();
    }
    __syncthreads();
}

// process one node-pair with one warp; weights from smem
__device__ __forceinline__ void node_pair(int nd0, int nd1, bool two, int lane,
                                          const float* sUi, const float* sUf,
                                          const float* sUo, const float* sUu,
                                          const float* sCv, float* shw, float* scw,
                                          float* saw, float cb0, float cb1,
                                          float* __restrict__ out)
{
    ((float4*)shw)[lane]         = ((const float4*)(g_h + (size_t)(2 * nd0 + 1) * HID))[lane];
    ((float4*)(shw + 128))[lane] = ((const float4*)(g_h + (size_t)(2 * nd1 + 1) * HID))[lane];
    ((float4*)scw)[lane]         = ((const float4*)(g_c + (size_t)(2 * nd0 + 1) * HID))[lane];
    ((float4*)(scw + 128))[lane] = ((const float4*)(g_c + (size_t)(2 * nd1 + 1) * HID))[lane];
    const float* wx0 = g_Wx + (size_t)nd0 * NGEMM;
    const float* wx1 = g_Wx + (size_t)nd1 * NGEMM;
    float xf00 = wx0[64 + lane],  xf01 = wx0[96 + lane];
    float xf10 = wx1[64 + lane],  xf11 = wx1[96 + lane];
    __syncwarp();

    // conv avg
    float a00 = cb0, a01 = cb1, a10 = cb0, a11 = cb1;
#pragma unroll 4
    for (int h = 0; h < 128; ++h) {
        float w0 = sCv[h * 64 + lane], w1 = sCv[h * 64 + lane + 32];
        float s0 = shw[h], s1 = shw[128 + h];
        a00 += s0 * w0; a01 += s0 * w1; a10 += s1 * w0; a11 += s1 * w1;
    }
    saw[lane] = a00; saw[lane + 32] = a01;
    saw[64 + lane] = a10; saw[96 + lane] = a11;

    // forget gates per child
    float fl00 = xf00, fl01 = xf01, fl10 = xf10, fl11 = xf11;
    float fr00 = xf00, fr01 = xf01, fr10 = xf10, fr11 = xf11;
#pragma unroll 4
    for (int h = 0; h < 64; ++h) {
        float w0 = sUf[h * 64 + lane], w1 = sUf[h * 64 + lane + 32];
        float l0 = shw[h], r0 = shw[64 + h];
        float l1 = shw[128 + h], r1 = shw[192 + h];
        fl00 += l0 * w0; fl01 += l0 * w1; fl10 += l1 * w0; fl11 += l1 * w1;
        fr00 += r0 * w0; fr01 += r0 * w1; fr10 += r1 * w0; fr11 += r1 * w1;
    }
    float sf00 = sigmoidf_(fl00) * scw[lane]       + sigmoidf_(fr00) * scw[64 + lane];
    float sf01 = sigmoidf_(fl01) * scw[lane + 32]  + sigmoidf_(fr01) * scw[96 + lane];
    float sf10 = sigmoidf_(fl10) * scw[128 + lane] + sigmoidf_(fr10) * scw[192 + lane];
    float sf11 = sigmoidf_(fl11) * scw[160 + lane] + sigmoidf_(fr11) * scw[224 + lane];
    __syncwarp();

    float zi00 = wx0[lane],       zi01 = wx0[lane + 32];
    float zi10 = wx1[lane],       zi11 = wx1[lane + 32];
    float zo00 = wx0[128 + lane], zo01 = wx0[160 + lane];
    float zo10 = wx1[128 + lane], zo11 = wx1[160 + lane];
    float zu00 = wx0[192 + lane], zu01 = wx0[224 + lane];
    float zu10 = wx1[192 + lane], zu11 = wx1[224 + lane];
#pragma unroll 2
    for (int h = 0; h < 64; ++h) {
        float wi0 = sUi[h * 64 + lane], wi1 = sUi[h * 64 + lane + 32];
        float wo0 = sUo[h * 64 + lane], wo1 = sUo[h * 64 + lane + 32];
        float wu0 = sUu[h * 64 + lane], wu1 = sUu[h * 64 + lane + 32];
        float q0 = saw[h], q1 = saw[64 + h];
        zi00 += q0 * wi0; zi01 += q0 * wi1; zi10 += q1 * wi0; zi11 += q1 * wi1;
        zo00 += q0 * wo0; zo01 += q0 * wo1; zo10 += q1 * wo0; zo11 += q1 * wo1;
        zu00 += q0 * wu0; zu01 += q0 * wu1; zu10 += q1 * wu0; zu11 += q1 * wu1;
    }
    float c0 = sf00 + sigmoidf_(zi00) * tanhf(zu00);
    float h0 = sigmoidf_(zo00) * tanhf(c0);
    g_c[(size_t)nd0 * HID + lane] = c0;
    g_h[(size_t)nd0 * HID + lane] = h0;
    float c1 = sf01 + sigmoidf_(zi01) * tanhf(zu01);
    float h1 = sigmoidf_(zo01) * tanhf(c1);
    g_c[(size_t)nd0 * HID + lane + 32] = c1;
    g_h[(size_t)nd0 * HID + lane + 32] = h1;
    if (nd0 == 0) {
        out[lane] = h0;  out[lane + 32] = h1;
        out[64 + lane] = c0; out[96 + lane] = c1;
    }
    if (two) {
        float c2 = sf10 + sigmoidf_(zi10) * tanhf(zu10);
        g_c[(size_t)nd1 * HID + lane] = c2;
        g_h[(size_t)nd1 * HID + lane] = sigmoidf_(zo10) * tanhf(c2);
        float c3 = sf11 + sigmoidf_(zi11) * tanhf(zu11);
        g_c[(size_t)nd1 * HID + lane + 32] = c3;
        g_h[(size_t)nd1 * HID + lane + 32] = sigmoidf_(zo11) * tanhf(c3);
    }
    __syncwarp();
}

__global__ void __launch_bounds__(TTHREADS, 1)
tree_kernel(const float* __restrict__ conv_b, float* __restrict__ out)
{
    extern __shared__ float ts[];
    const int tid = threadIdx.x, lane = tid & 31, warp = tid >> 5;
    const int gw = blockIdx.x * TWARPS + warp;
    float* shw = ts + TS_WB + warp * 640;
    float* scw = shw + 256;
    float* saw = shw + 512;
    const float cb0 = conv_b[lane], cb1 = conv_b[lane + 32];

    // stage weights into smem
    for (int i = tid; i < 4096; i += TTHREADS) {
        ts[TS_UF + i] = g_Uft[i];
        ts[TS_UI + i] = g_Uit[i];
        ts[TS_UO + i] = g_Uot[i];
        ts[TS_UU + i] = g_Uut[i];
    }
    for (int i = tid; i < 8192; i += TTHREADS) ts[TS_CV + i] = g_convWt[i];

    // leaves
    for (int idx = blockIdx.x * TTHREADS + tid; idx < NLEAF * HID; idx += TGRID * TTHREADS) {
        int node = (NLEAF - 1) + (idx >> 6);
        int o = idx & 63;
        const float* wx = g_Wx + (size_t)node * NGEMM;
        float zi = wx[o]       + g_v[o];
        float zo = wx[128 + o] + g_v[64 + o];
        float zu = wx[192 + o] + g_v[128 + o];
        float c = sigmoidf_(zi) * tanhf(zu);
        g_c[(size_t)node * HID + o] = c;
        g_h[(size_t)node * HID + o] = sigmoidf_(zo) * tanhf(c);
    }
    int bi = 0;
    gridbar(bi++);

    // grid-wide levels d = 12..5
    for (int d = DEPTH - 2; d >= 5; --d) {
        const int n = 1 << d, start = n - 1;
        for (int j = gw * 2; j < n; j += TW * 2) {
            const bool two = (j + 1 < n);
            node_pair(start + j, start + j + (two ? 1 : 0), two, lane,
                      ts + TS_UI, ts + TS_UF, ts + TS_UO, ts + TS_UU, ts + TS_CV,
                      shw, scw, saw, cb0, cb1, out);
        }
        gridbar(bi++);
    }

    // top levels d = 4..0 in block 0 only
    __syncthreads();
    if (blockIdx.x != 0) {
        if (tid == 0) { __threadfence(); atomicAdd(&g_bar[bi], 1u); }
        return;
    }
    if (tid == 0) {
        __threadfence();
        atomicAdd(&g_bar[bi], 1u);
        while (*(volatile unsigned*)&g_bar[bi] < (unsigned)TGRID) { __nanosleep(64); }
        __threadfence();
    }
    __syncthreads();

    for (int d = 4; d >= 0; --d) {
        const int n = 1 << d, start = n - 1;
        for (int j = warp * 2; j < n; j += TWARPS * 2) {
            const bool two = (j + 1 < n);
            node_pair(start + j, start + j + (two ? 1 : 0), two, lane,
                      ts + TS_UI, ts + TS_UF, ts + TS_UO, ts + TS_UU, ts + TS_CV,
                      shw, scw, saw, cb0, cb1, out);
        }
        __syncthreads();
    }
}

// ---------------- launch ----------------
extern "C" void kernel_launch(void* const* d_in, const int* in_sizes, int n_in,
                              void* d_out, int out_size)
{
    const float* inputs = (const float*)d_in[0];
    const float* Wx_w   = (const float*)d_in[1];
    const float* Wx_b   = (const float*)d_in[2];
    const float* U_i    = (const float*)d_in[3];
    const float* U_f    = (const float*)d_in[4];
    const float* U_o    = (const float*)d_in[5];
    const float* U_u    = (const float*)d_in[6];
    const float* convW  = (const float*)d_in[7];
    const float* conv_b = (const float*)d_in[8];
    float* out = (float*)d_out;

    cudaFuncSetAttribute(gemm_kernel, cudaFuncAttributeMaxDynamicSharedMemorySize, GEMM_SMEM);
    cudaFuncSetAttribute(tree_kernel, cudaFuncAttributeMaxDynamicSharedMemorySize, TREE_SMEM);

    prep_kernel<<<512, 256>>>(Wx_w, U_i, U_f, U_o, U_u, convW, conv_b);
    gemm_kernel<<<(NNODES + BM - 1) / BM, THREADS, GEMM_SMEM>>>(inputs, Wx_b);
    tree_kernel<<<TGRID, TTHREADS, TREE_SMEM>>>(conv_b, out);
}

// round 6
// speedup vs baseline: 1.3041x; 1.0117x over previous
#include <cuda_runtime.h>
#include <cstdint>

// ---------------- problem constants ----------------
#define HID 64
#define INDIM 4800
#define DEPTH 14
#define NNODES 16383
#define NGEMM 256
#define NLEAF 8192

// ---------------- device scratch ----------------
__device__ float g_Wx[NNODES * NGEMM];
__device__ float g_Br[NGEMM * INDIM];
__device__ float g_h[NNODES * HID];
__device__ float g_c[NNODES * HID];
__device__ float g_Uit[HID * HID];
__device__ float g_Uft[HID * HID];
__device__ float g_Uot[HID * HID];
__device__ float g_Uut[HID * HID];
__device__ float g_convWt[2 * HID * HID];
__device__ float g_v[3 * HID];
__device__ unsigned g_bar[32];     // zero at load; block 0 re-zeros at end of every run

// ---------------- helpers ----------------
__device__ __forceinline__ float sigmoidf_(float x) { return 1.f / (1.f + __expf(-x)); }
__device__ __forceinline__ float rna_tf32(float x) {
    unsigned r; asm("cvt.rna.tf32.f32 %0, %1;" : "=r"(r) : "f"(x));
    return __uint_as_float(r);
}
__device__ __forceinline__ unsigned f2tf32(float x) {
    unsigned r; asm("cvt.rna.tf32.f32 %0, %1;" : "=r"(r) : "f"(x));
    return r;
}
__device__ __forceinline__ void mma_tf32(float* d, const unsigned* a, const unsigned* b) {
    asm volatile(
        "mma.sync.aligned.m16n8k8.row.col.f32.tf32.tf32.f32 "
        "{%0,%1,%2,%3},{%4,%5,%6,%7},{%8,%9},{%0,%1,%2,%3};"
        : "+f"(d[0]), "+f"(d[1]), "+f"(d[2]), "+f"(d[3])
        : "r"(a[0]), "r"(a[1]), "r"(a[2]), "r"(a[3]), "r"(b[0]), "r"(b[1]));
}
__device__ __forceinline__ void cp_async16(float* smem_dst, const float* gsrc) {
    unsigned sa = (unsigned)__cvta_generic_to_shared(smem_dst);
    asm volatile("cp.async.cg.shared.global [%0], [%1], 16;\n" :: "r"(sa), "l"(gsrc));
}
__device__ __forceinline__ void cp_commit() { asm volatile("cp.async.commit_group;\n" ::: "memory"); }

// ---------------- geometry ----------------
#define TGRID 148
#define THREADS 512
#define TWARPS 16
#define TW (TGRID * TWARPS)

// GEMM: 128x256 block tile, BK=24, 3 stages
#define GBLOCKS 128
#define BM 128
#define BN 256
#define BK 24
#define NK (INDIM / BK)        // 200
#define PADK 28                // 28r mod 32 = {0,28,24,20,16,12,8,4} -> conflict-free
#define AST (BM * PADK)        // 3584
#define BST (BN * PADK)        // 7168
#define STF (AST + BST)        // 10752 floats = 43008 B
#define NSTG 3

// tree smem layout (floats)
#define TS_UF 0
#define TS_UI 4096
#define TS_UO 8192
#define TS_UU 12288
#define TS_CV 16384
#define TS_WB 24576
#define SMEM_FLOATS (TS_WB + TWARPS * 640)     // 34816
#define SMEM_BYTES (SMEM_FLOATS * 4)           // 139264 (>= 3*STF*4 = 129024)

__device__ __forceinline__ void gridbar(int i) {
    __syncthreads();
    if (threadIdx.x == 0) {
        __threadfence();
        unsigned prev = atomicAdd(&g_bar[i], 1u);
        if (prev + 1u < (unsigned)TGRID) {
            while (*(volatile unsigned*)&g_bar[i] < (unsigned)TGRID) { __nanosleep(64); }
        }
        __threadfence();
    }
    __syncthreads();
}

// ---------------- one node-pair on one warp (weights in smem) ----------------
__device__ __forceinline__ void node_pair(int nd0, int nd1, bool two, int lane,
                                          const float* sUi, const float* sUf,
                                          const float* sUo, const float* sUu,
                                          const float* sCv, float* shw, float* scw,
                                          float* saw, float cb0, float cb1,
                                          float* __restrict__ out)
{
    ((float4*)shw)[lane]         = ((const float4*)(g_h + (size_t)(2 * nd0 + 1) * HID))[lane];
    ((float4*)(shw + 128))[lane] = ((const float4*)(g_h + (size_t)(2 * nd1 + 1) * HID))[lane];
    ((float4*)scw)[lane]         = ((const float4*)(g_c + (size_t)(2 * nd0 + 1) * HID))[lane];
    ((float4*)(scw + 128))[lane] = ((const float4*)(g_c + (size_t)(2 * nd1 + 1) * HID))[lane];
    const float* wx0 = g_Wx + (size_t)nd0 * NGEMM;
    const float* wx1 = g_Wx + (size_t)nd1 * NGEMM;
    float xf00 = wx0[64 + lane],  xf01 = wx0[96 + lane];
    float xf10 = wx1[64 + lane],  xf11 = wx1[96 + lane];
    __syncwarp();

    float a00 = cb0, a01 = cb1, a10 = cb0, a11 = cb1;
#pragma unroll 4
    for (int h = 0; h < 128; ++h) {
        float w0 = sCv[h * 64 + lane], w1 = sCv[h * 64 + lane + 32];
        float s0 = shw[h], s1 = shw[128 + h];
        a00 += s0 * w0; a01 += s0 * w1; a10 += s1 * w0; a11 += s1 * w1;
    }
    saw[lane] = a00; saw[lane + 32] = a01;
    saw[64 + lane] = a10; saw[96 + lane] = a11;

    float fl00 = xf00, fl01 = xf01, fl10 = xf10, fl11 = xf11;
    float fr00 = xf00, fr01 = xf01, fr10 = xf10, fr11 = xf11;
#pragma unroll 4
    for (int h = 0; h < 64; ++h) {
        float w0 = sUf[h * 64 + lane], w1 = sUf[h * 64 + lane + 32];
        float l0 = shw[h], r0 = shw[64 + h];
        float l1 = shw[128 + h], r1 = shw[192 + h];
        fl00 += l0 * w0; fl01 += l0 * w1; fl10 += l1 * w0; fl11 += l1 * w1;
        fr00 += r0 * w0; fr01 += r0 * w1; fr10 += r1 * w0; fr11 += r1 * w1;
    }
    float sf00 = sigmoidf_(fl00) * scw[lane]       + sigmoidf_(fr00) * scw[64 + lane];
    float sf01 = sigmoidf_(fl01) * scw[lane + 32]  + sigmoidf_(fr01) * scw[96 + lane];
    float sf10 = sigmoidf_(fl10) * scw[128 + lane] + sigmoidf_(fr10) * scw[192 + lane];
    float sf11 = sigmoidf_(fl11) * scw[160 + lane] + sigmoidf_(fr11) * scw[224 + lane];
    __syncwarp();

    float zi00 = wx0[lane],       zi01 = wx0[lane + 32];
    float zi10 = wx1[lane],       zi11 = wx1[lane + 32];
    float zo00 = wx0[128 + lane], zo01 = wx0[160 + lane];
    float zo10 = wx1[128 + lane], zo11 = wx1[160 + lane];
    float zu00 = wx0[192 + lane], zu01 = wx0[224 + lane];
    float zu10 = wx1[192 + lane], zu11 = wx1[224 + lane];
#pragma unroll 2
    for (int h = 0; h < 64; ++h) {
        float wi0 = sUi[h * 64 + lane], wi1 = sUi[h * 64 + lane + 32];
        float wo0 = sUo[h * 64 + lane], wo1 = sUo[h * 64 + lane + 32];
        float wu0 = sUu[h * 64 + lane], wu1 = sUu[h * 64 + lane + 32];
        float q0 = saw[h], q1 = saw[64 + h];
        zi00 += q0 * wi0; zi01 += q0 * wi1; zi10 += q1 * wi0; zi11 += q1 * wi1;
        zo00 += q0 * wo0; zo01 += q0 * wo1; zo10 += q1 * wo0; zo11 += q1 * wo1;
        zu00 += q0 * wu0; zu01 += q0 * wu1; zu10 += q1 * wu0; zu11 += q1 * wu1;
    }
    float c0 = sf00 + sigmoidf_(zi00) * tanhf(zu00);
    float h0 = sigmoidf_(zo00) * tanhf(c0);
    g_c[(size_t)nd0 * HID + lane] = c0;
    g_h[(size_t)nd0 * HID + lane] = h0;
    float c1 = sf01 + sigmoidf_(zi01) * tanhf(zu01);
    float h1 = sigmoidf_(zo01) * tanhf(c1);
    g_c[(size_t)nd0 * HID + lane + 32] = c1;
    g_h[(size_t)nd0 * HID + lane + 32] = h1;
    if (nd0 == 0) {
        out[lane] = h0;  out[lane + 32] = h1;
        out[64 + lane] = c0; out[96 + lane] = c1;
    }
    if (two) {
        float c2 = sf10 + sigmoidf_(zi10) * tanhf(zu10);
        g_c[(size_t)nd1 * HID + lane] = c2;
        g_h[(size_t)nd1 * HID + lane] = sigmoidf_(zo10) * tanhf(c2);
        float c3 = sf11 + sigmoidf_(zi11) * tanhf(zu11);
        g_c[(size_t)nd1 * HID + lane + 32] = c3;
        g_h[(size_t)nd1 * HID + lane + 32] = sigmoidf_(zo11) * tanhf(c3);
    }
    __syncwarp();
}

// ---------------- the mega-kernel ----------------
__global__ void __launch_bounds__(THREADS, 1)
mega_kernel(const float* __restrict__ A,      // inputs [NNODES, INDIM]
            const float* __restrict__ Wx_w,   // [256, INDIM]
            const float* __restrict__ Wx_b,   // [256]
            const float* __restrict__ U_i, const float* __restrict__ U_f,
            const float* __restrict__ U_o, const float* __restrict__ U_u,
            const float* __restrict__ convW, const float* __restrict__ conv_b,
            float* __restrict__ out)
{
    extern __shared__ float sm[];
    const int tid  = threadIdx.x;
    const int lane = tid & 31;
    const int warp = tid >> 5;
    const int t0 = blockIdx.x * THREADS + tid;
    const int nt = TGRID * THREADS;

    // ========== phase 0: prep ==========
    for (int i = t0; i < NGEMM * INDIM / 4; i += nt) {
        float4 v = ((const float4*)Wx_w)[i];
        v.x = rna_tf32(v.x); v.y = rna_tf32(v.y);
        v.z = rna_tf32(v.z); v.w = rna_tf32(v.w);
        ((float4*)g_Br)[i] = v;
    }
    for (int idx = t0; idx < HID * HID; idx += nt) {
        int o = idx >> 6, h = idx & 63;
        g_Uit[h * HID + o] = U_i[idx];
        g_Uft[h * HID + o] = U_f[idx];
        g_Uot[h * HID + o] = U_o[idx];
        g_Uut[h * HID + o] = U_u[idx];
    }
    for (int idx = t0; idx < 2 * HID * HID; idx += nt) {
        int o = idx >> 7, kh = idx & 127;
        g_convWt[kh * HID + o] = convW[idx];
    }
    if (t0 < HID) {
        float vi = 0.f, vo = 0.f, vu = 0.f;
        for (int h = 0; h < HID; ++h) {
            float b = conv_b[h];
            vi += b * U_i[t0 * HID + h];
            vo += b * U_o[t0 * HID + h];
            vu += b * U_u[t0 * HID + h];
        }
        g_v[t0] = vi; g_v[HID + t0] = vo; g_v[2 * HID + t0] = vu;
    }
    gridbar(0);

    // ========== phase 1: GEMM (blocks 0..127) ==========
    if (blockIdx.x < GBLOCKS) {
        const int m0 = (warp >> 2) * 32;
        const int n0 = (warp & 3) * 64;
        const int bm = blockIdx.x * BM;

        float acc[2][8][4];
#pragma unroll
        for (int i = 0; i < 2; ++i)
#pragma unroll
            for (int j = 0; j < 8; ++j)
#pragma unroll
                for (int k = 0; k < 4; ++k) acc[i][j][k] = 0.f;

        auto issue = [&](int t) {
            float* stg = sm + (t % NSTG) * STF;
            const int k0 = t * BK;
#pragma unroll
            for (int i = 0; i < 5; ++i) {
                int idx = tid + i * THREADS;          // 0..2559 used of 2304
                if (idx < 768) {                      // A: 128 rows x 6 float4
                    int row = idx / 6, c4 = idx % 6;
                    int gr = bm + row; if (gr > NNODES - 1) gr = NNODES - 1;
                    cp_async16(stg + row * PADK + c4 * 4,
                               A + (size_t)gr * INDIM + k0 + c4 * 4);
                } else if (idx < 2304) {              // B: 256 rows x 6 float4
                    int cb = idx - 768;
                    int row = cb / 6, c4 = cb % 6;
                    cp_async16(stg + AST + row * PADK + c4 * 4,
                               g_Br + (size_t)row * INDIM + k0 + c4 * 4);
                }
            }
            cp_commit();
        };

        issue(0); issue(1);

        for (int s = 0; s < NK; ++s) {
            if (s == NK - 1) { asm volatile("cp.async.wait_group 0;" ::: "memory"); }
            else             { asm volatile("cp.async.wait_group 1;" ::: "memory"); }
            __syncthreads();
            if (s + 2 < NK) issue(s + 2);

            const float* tA = sm + (s % NSTG) * STF;
            const float* tB = tA + AST;
            const int r  = lane >> 2;
            const int cc = lane & 3;

#pragma unroll
            for (int ks = 0; ks < 3; ++ks) {
                const int kcol = ks * 8;
                unsigned af[2][4], bf[8][2];
#pragma unroll
                for (int im = 0; im < 2; ++im) {
                    const float* base = tA + (m0 + im * 16 + r) * PADK + kcol + cc;
                    af[im][0] = f2tf32(base[0]);
                    af[im][1] = f2tf32(base[8 * PADK]);
                    af[im][2] = f2tf32(base[4]);
                    af[im][3] = f2tf32(base[8 * PADK + 4]);
                }
#pragma unroll
                for (int in = 0; in < 8; ++in) {
                    const float* bb = tB + (n0 + in * 8 + r) * PADK + kcol + cc;
                    bf[in][0] = __float_as_uint(bb[0]);
                    bf[in][1] = __float_as_uint(bb[4]);
                }
#pragma unroll
                for (int im = 0; im < 2; ++im)
#pragma unroll
                    for (int in = 0; in < 8; ++in)
                        mma_tf32(acc[im][in], af[im], bf[in]);
            }
        }

#pragma unroll
        for (int im = 0; im < 2; ++im) {
#pragma unroll
            for (int in = 0; in < 8; ++in) {
                int rr = bm + m0 + im * 16 + (lane >> 2);
                int cg = n0 + in * 8 + (lane & 3) * 2;
                float b0 = Wx_b[cg], b1 = Wx_b[cg + 1];
                if (rr < NNODES) {
                    float2 v = make_float2(acc[im][in][0] + b0, acc[im][in][1] + b1);
                    *(float2*)(g_Wx + (size_t)rr * NGEMM + cg) = v;
                }
                int rr2 = rr + 8;
                if (rr2 < NNODES) {
                    float2 v = make_float2(acc[im][in][2] + b0, acc[im][in][3] + b1);
                    *(float2*)(g_Wx + (size_t)rr2 * NGEMM + cg) = v;
                }
            }
        }
        __syncthreads();    // smem stage reads done before tree staging overwrites
    }

    // stage tree weights into smem (gmem -> smem; blocks >=128 overlap gemm)
    for (int i = tid; i < 4096; i += THREADS) {
        sm[TS_UF + i] = g_Uft[i];
        sm[TS_UI + i] = g_Uit[i];
        sm[TS_UO + i] = g_Uot[i];
        sm[TS_UU + i] = g_Uut[i];
    }
    for (int i = tid; i < 8192; i += THREADS) sm[TS_CV + i] = g_convWt[i];
    gridbar(1);

    // ========== phase 2: leaves ==========
    for (int idx = t0; idx < NLEAF * HID; idx += nt) {
        int node = (NLEAF - 1) + (idx >> 6);
        int o = idx & 63;
        const float* wx = g_Wx + (size_t)node * NGEMM;
        float zi = wx[o]       + g_v[o];
        float zo = wx[128 + o] + g_v[64 + o];
        float zu = wx[192 + o] + g_v[128 + o];
        float c = sigmoidf_(zi) * tanhf(zu);
        g_c[(size_t)node * HID + o] = c;
        g_h[(size_t)node * HID + o] = sigmoidf_(zo) * tanhf(c);
    }
    int bi = 2;
    gridbar(bi++);

    // ========== phase 3: levels d = 12..5, grid-wide ==========
    const int gw = blockIdx.x * TWARPS + warp;
    float* shw = sm + TS_WB + warp * 640;
    float* scw = shw + 256;
    float* saw = shw + 512;
    const float cb0 = conv_b[lane], cb1 = conv_b[lane + 32];

    for (int d = DEPTH - 2; d >= 5; --d) {
        const int n = 1 << d, start = n - 1;
        for (int j = gw * 2; j < n; j += TW * 2) {
            const bool two = (j + 1 < n);
            node_pair(start + j, start + j + (two ? 1 : 0), two, lane,
                      sm + TS_UI, sm + TS_UF, sm + TS_UO, sm + TS_UU, sm + TS_CV,
                      shw, scw, saw, cb0, cb1, out);
        }
        gridbar(bi++);          // bi 3..10
    }

    // ========== phase 4: levels d = 4..0, block 0 only ==========
    __syncthreads();
    if (blockIdx.x != 0) {
        if (tid == 0) { __threadfence(); atomicAdd(&g_bar[bi], 1u); }
        return;
    }
    if (tid == 0) {
        __threadfence();
        atomicAdd(&g_bar[bi], 1u);
        while (*(volatile unsigned*)&g_bar[bi] < (unsigned)TGRID) { __nanosleep(64); }
        __threadfence();
    }
    __syncthreads();

    for (int d = 4; d >= 0; --d) {
        const int n = 1 << d, start = n - 1;
        for (int j = warp * 2; j < n; j += TWARPS * 2) {
            const bool two = (j + 1 < n);
            node_pair(start + j, start + j + (two ? 1 : 0), two, lane,
                      sm + TS_UI, sm + TS_UF, sm + TS_UO, sm + TS_UU, sm + TS_CV,
                      shw, scw, saw, cb0, cb1, out);
        }
        __syncthreads();
    }

    // reset grid barriers for the next (graph-replayed) run
    if (tid < 32) g_bar[tid] = 0;
}

// ---------------- launch ----------------
extern "C" void kernel_launch(void* const* d_in, const int* in_sizes, int n_in,
                              void* d_out, int out_size)
{
    const float* inputs = (const float*)d_in[0];
    const float* Wx_w   = (const float*)d_in[1];
    const float* Wx_b   = (const float*)d_in[2];
    const float* U_i    = (const float*)d_in[3];
    const float* U_f    = (const float*)d_in[4];
    const float* U_o    = (const float*)d_in[5];
    const float* U_u    = (const float*)d_in[6];
    const float* convW  = (const float*)d_in[7];
    const float* conv_b = (const float*)d_in[8];
    float* out = (float*)d_out;

    cudaFuncSetAttribute(mega_kernel, cudaFuncAttributeMaxDynamicSharedMemorySize, SMEM_BYTES);
    mega_kernel<<<TGRID, THREADS, SMEM_BYTES>>>(inputs, Wx_w, Wx_b, U_i, U_f, U_o, U_u,
                                                convW, conv_b, out);
}

// round 7
// speedup vs baseline: 2.1687x; 1.6630x over previous
#include <cuda_runtime.h>
#include <cuda_fp16.h>
#include <cstdint>

// ---------------- problem constants ----------------
#define HID 64
#define INDIM 4800
#define DEPTH 14
#define NNODES 16383
#define NGEMM 256
#define NLEAF 8192

// ---------------- device scratch ----------------
__device__ float g_Wx[NNODES * NGEMM];
__device__ __half g_Bh[NGEMM * INDIM];     // fp16 copy of Wx_w
__device__ float g_h[NNODES * HID];
__device__ float g_c[NNODES * HID];
__device__ float g_Uit[HID * HID];
__device__ float g_Uft[HID * HID];
__device__ float g_Uot[HID * HID];
__device__ float g_Uut[HID * HID];
__device__ float g_convWt[2 * HID * HID];
__device__ float g_v[3 * HID];
__device__ unsigned g_bar[32];

// ---------------- helpers ----------------
__device__ __forceinline__ float sigmoidf_(float x) { return 1.f / (1.f + __expf(-x)); }

__device__ __forceinline__ void mma_f16(float* d, const unsigned* a, const unsigned* b) {
    asm volatile(
        "mma.sync.aligned.m16n8k16.row.col.f32.f16.f16.f32 "
        "{%0,%1,%2,%3},{%4,%5,%6,%7},{%8,%9},{%0,%1,%2,%3};"
        : "+f"(d[0]), "+f"(d[1]), "+f"(d[2]), "+f"(d[3])
        : "r"(a[0]), "r"(a[1]), "r"(a[2]), "r"(a[3]), "r"(b[0]), "r"(b[1]));
}
__device__ __forceinline__ void cp_async16h(__half* smem_dst, const __half* gsrc) {
    unsigned sa = (unsigned)__cvta_generic_to_shared(smem_dst);
    asm volatile("cp.async.cg.shared.global [%0], [%1], 16;\n" :: "r"(sa), "l"(gsrc));
}
__device__ __forceinline__ void cp_commit() { asm volatile("cp.async.commit_group;\n" ::: "memory"); }

// ---------------- geometry ----------------
#define TGRID 148
#define THREADS 512
#define TWARPS 16
#define TW (TGRID * TWARPS)

// GEMM: 128x256 tile, fp16 operands, BK=32
#define GBLOCKS 128
#define BM 128
#define BN 256
#define BK 32
#define NK (INDIM / BK)        // 150
#define PADH 40                // halves per row (32 + 8) -> conflict-free u32 frag loads
#define A_STH (BM * PADH)      // 5120 halves / stage (2 stages)
#define B_STH (BN * PADH)      // 10240 halves / stage (4 stages)
#define B_BASEH (2 * A_STH)    // 10240

// tree smem layout (floats)
#define TS_UF 0
#define TS_UI 4096
#define TS_UO 8192
#define TS_UU 12288
#define TS_CV 16384
#define TS_WB 24576
#define SMEM_FLOATS (TS_WB + TWARPS * 640)     // 34816
#define SMEM_BYTES (SMEM_FLOATS * 4)           // 139264 B (gemm needs 51200 halves = 102400 B)

__device__ __forceinline__ void gridbar(int i) {
    __syncthreads();
    if (threadIdx.x == 0) {
        __threadfence();
        unsigned prev = atomicAdd(&g_bar[i], 1u);
        if (prev + 1u < (unsigned)TGRID) {
            while (*(volatile unsigned*)&g_bar[i] < (unsigned)TGRID) { __nanosleep(64); }
        }
        __threadfence();
    }
    __syncthreads();
}

// ---------------- one node-pair on one warp (weights in smem) ----------------
__device__ __forceinline__ void node_pair(int nd0, int nd1, bool two, int lane,
                                          const float* sUi, const float* sUf,
                                          const float* sUo, const float* sUu,
                                          const float* sCv, float* shw, float* scw,
                                          float* saw, float cb0, float cb1,
                                          float* __restrict__ out)
{
    ((float4*)shw)[lane]         = ((const float4*)(g_h + (size_t)(2 * nd0 + 1) * HID))[lane];
    ((float4*)(shw + 128))[lane] = ((const float4*)(g_h + (size_t)(2 * nd1 + 1) * HID))[lane];
    ((float4*)scw)[lane]         = ((const float4*)(g_c + (size_t)(2 * nd0 + 1) * HID))[lane];
    ((float4*)(scw + 128))[lane] = ((const float4*)(g_c + (size_t)(2 * nd1 + 1) * HID))[lane];
    const float* wx0 = g_Wx + (size_t)nd0 * NGEMM;
    const float* wx1 = g_Wx + (size_t)nd1 * NGEMM;
    float xf00 = wx0[64 + lane],  xf01 = wx0[96 + lane];
    float xf10 = wx1[64 + lane],  xf11 = wx1[96 + lane];
    __syncwarp();

    float a00 = cb0, a01 = cb1, a10 = cb0, a11 = cb1;
#pragma unroll 4
    for (int h = 0; h < 128; ++h) {
        float w0 = sCv[h * 64 + lane], w1 = sCv[h * 64 + lane + 32];
        float s0 = shw[h], s1 = shw[128 + h];
        a00 += s0 * w0; a01 += s0 * w1; a10 += s1 * w0; a11 += s1 * w1;
    }
    saw[lane] = a00; saw[lane + 32] = a01;
    saw[64 + lane] = a10; saw[96 + lane] = a11;

    float fl00 = xf00, fl01 = xf01, fl10 = xf10, fl11 = xf11;
    float fr00 = xf00, fr01 = xf01, fr10 = xf10, fr11 = xf11;
#pragma unroll 4
    for (int h = 0; h < 64; ++h) {
        float w0 = sUf[h * 64 + lane], w1 = sUf[h * 64 + lane + 32];
        float l0 = shw[h], r0 = shw[64 + h];
        float l1 = shw[128 + h], r1 = shw[192 + h];
        fl00 += l0 * w0; fl01 += l0 * w1; fl10 += l1 * w0; fl11 += l1 * w1;
        fr00 += r0 * w0; fr01 += r0 * w1; fr10 += r1 * w0; fr11 += r1 * w1;
    }
    float sf00 = sigmoidf_(fl00) * scw[lane]       + sigmoidf_(fr00) * scw[64 + lane];
    float sf01 = sigmoidf_(fl01) * scw[lane + 32]  + sigmoidf_(fr01) * scw[96 + lane];
    float sf10 = sigmoidf_(fl10) * scw[128 + lane] + sigmoidf_(fr10) * scw[192 + lane];
    float sf11 = sigmoidf_(fl11) * scw[160 + lane] + sigmoidf_(fr11) * scw[224 + lane];
    __syncwarp();

    float zi00 = wx0[lane],       zi01 = wx0[lane + 32];
    float zi10 = wx1[lane],       zi11 = wx1[lane + 32];
    float zo00 = wx0[128 + lane], zo01 = wx0[160 + lane];
    float zo10 = wx1[128 + lane], zo11 = wx1[160 + lane];
    float zu00 = wx0[192 + lane], zu01 = wx0[224 + lane];
    float zu10 = wx1[192 + lane], zu11 = wx1[224 + lane];
#pragma unroll 2
    for (int h = 0; h < 64; ++h) {
        float wi0 = sUi[h * 64 + lane], wi1 = sUi[h * 64 + lane + 32];
        float wo0 = sUo[h * 64 + lane], wo1 = sUo[h * 64 + lane + 32];
        float wu0 = sUu[h * 64 + lane], wu1 = sUu[h * 64 + lane + 32];
        float q0 = saw[h], q1 = saw[64 + h];
        zi00 += q0 * wi0; zi01 += q0 * wi1; zi10 += q1 * wi0; zi11 += q1 * wi1;
        zo00 += q0 * wo0; zo01 += q0 * wo1; zo10 += q1 * wo0; zo11 += q1 * wo1;
        zu00 += q0 * wu0; zu01 += q0 * wu1; zu10 += q1 * wu0; zu11 += q1 * wu1;
    }
    float c0 = sf00 + sigmoidf_(zi00) * tanhf(zu00);
    float h0 = sigmoidf_(zo00) * tanhf(c0);
    g_c[(size_t)nd0 * HID + lane] = c0;
    g_h[(size_t)nd0 * HID + lane] = h0;
    float c1 = sf01 + sigmoidf_(zi01) * tanhf(zu01);
    float h1 = sigmoidf_(zo01) * tanhf(c1);
    g_c[(size_t)nd0 * HID + lane + 32] = c1;
    g_h[(size_t)nd0 * HID + lane + 32] = h1;
    if (nd0 == 0) {
        out[lane] = h0;  out[lane + 32] = h1;
        out[64 + lane] = c0; out[96 + lane] = c1;
    }
    if (two) {
        float c2 = sf10 + sigmoidf_(zi10) * tanhf(zu10);
        g_c[(size_t)nd1 * HID + lane] = c2;
        g_h[(size_t)nd1 * HID + lane] = sigmoidf_(zo10) * tanhf(c2);
        float c3 = sf11 + sigmoidf_(zi11) * tanhf(zu11);
        g_c[(size_t)nd1 * HID + lane + 32] = c3;
        g_h[(size_t)nd1 * HID + lane + 32] = sigmoidf_(zo11) * tanhf(c3);
    }
    __syncwarp();
}

// ---------------- the mega-kernel ----------------
__global__ void __launch_bounds__(THREADS, 1)
mega_kernel(const float* __restrict__ A,      // inputs [NNODES, INDIM]
            const float* __restrict__ Wx_w,
            const float* __restrict__ Wx_b,
            const float* __restrict__ U_i, const float* __restrict__ U_f,
            const float* __restrict__ U_o, const float* __restrict__ U_u,
            const float* __restrict__ convW, const float* __restrict__ conv_b,
            float* __restrict__ out)
{
    extern __shared__ float sm[];
    __half* smh = (__half*)sm;
    const int tid  = threadIdx.x;
    const int lane = tid & 31;
    const int warp = tid >> 5;
    const int t0 = blockIdx.x * THREADS + tid;
    const int nt = TGRID * THREADS;

    // ========== phase 0: prep ==========
    // fp16 copy of Wx_w (RN)
    for (int i = t0; i < NGEMM * INDIM / 4; i += nt) {
        float4 v = ((const float4*)Wx_w)[i];
        __half2 h0 = __floats2half2_rn(v.x, v.y);
        __half2 h1 = __floats2half2_rn(v.z, v.w);
        uint2 pk;
        pk.x = *(unsigned*)&h0;
        pk.y = *(unsigned*)&h1;
        ((uint2*)g_Bh)[i] = pk;
    }
    for (int idx = t0; idx < HID * HID; idx += nt) {
        int o = idx >> 6, h = idx & 63;
        g_Uit[h * HID + o] = U_i[idx];
        g_Uft[h * HID + o] = U_f[idx];
        g_Uot[h * HID + o] = U_o[idx];
        g_Uut[h * HID + o] = U_u[idx];
    }
    for (int idx = t0; idx < 2 * HID * HID; idx += nt) {
        int o = idx >> 7, kh = idx & 127;
        g_convWt[kh * HID + o] = convW[idx];
    }
    if (t0 < HID) {
        float vi = 0.f, vo = 0.f, vu = 0.f;
        for (int h = 0; h < HID; ++h) {
            float b = conv_b[h];
            vi += b * U_i[t0 * HID + h];
            vo += b * U_o[t0 * HID + h];
            vu += b * U_u[t0 * HID + h];
        }
        g_v[t0] = vi; g_v[HID + t0] = vo; g_v[2 * HID + t0] = vu;
    }
    gridbar(0);

    // ========== phase 1: fp16 GEMM (blocks 0..127) ==========
    if (blockIdx.x < GBLOCKS) {
        const int m0 = (warp >> 2) * 32;
        const int n0 = (warp & 3) * 64;
        const int bm = blockIdx.x * BM;
        const int arow = tid >> 2;          // 0..127
        const int aq   = tid & 3;           // 0..3 (8-half chunk)
        int agr = bm + arow; if (agr > NNODES - 1) agr = NNODES - 1;
        const float* agp = A + (size_t)agr * INDIM + aq * 8;

        float acc[2][8][4];
#pragma unroll
        for (int i = 0; i < 2; ++i)
#pragma unroll
            for (int j = 0; j < 8; ++j)
#pragma unroll
                for (int k = 0; k < 4; ++k) acc[i][j][k] = 0.f;

        float ar[8];
        auto ldgA = [&](int t) {
            const float4* p = (const float4*)(agp + t * BK);
            float4 u = p[0], v = p[1];
            ar[0] = u.x; ar[1] = u.y; ar[2] = u.z; ar[3] = u.w;
            ar[4] = v.x; ar[5] = v.y; ar[6] = v.z; ar[7] = v.w;
        };
        auto stsA = [&](int t) {
            __half2 p0 = __floats2half2_rn(ar[0], ar[1]);
            __half2 p1 = __floats2half2_rn(ar[2], ar[3]);
            __half2 p2 = __floats2half2_rn(ar[4], ar[5]);
            __half2 p3 = __floats2half2_rn(ar[6], ar[7]);
            uint4 pk;
            pk.x = *(unsigned*)&p0; pk.y = *(unsigned*)&p1;
            pk.z = *(unsigned*)&p2; pk.w = *(unsigned*)&p3;
            *(uint4*)(smh + (t & 1) * A_STH + arow * PADH + aq * 8) = pk;
        };
        auto issueB = [&](int t) {
            __half* stg = smh + B_BASEH + (t & 3) * B_STH;
            const int k0 = t * BK;
#pragma unroll
            for (int j = 0; j < 2; ++j) {
                int idx = tid + j * THREADS;    // 0..1023
                int row = idx >> 2, c = idx & 3;
                cp_async16h(stg + row * PADH + c * 8,
                            g_Bh + (size_t)row * INDIM + k0 + c * 8);
            }
            cp_commit();
        };

        ldgA(0);
        issueB(0); issueB(1);

        const int gid = lane >> 2, tig = lane & 3;

        for (int s = 0; s < NK; ++s) {
            stsA(s);
            if (s + 1 < NK) ldgA(s + 1);
            if (s + 2 < NK) issueB(s + 2); else cp_commit();
            asm volatile("cp.async.wait_group 2;" ::: "memory");
            __syncthreads();

            const __half* tA = smh + (s & 1) * A_STH;
            const __half* tB = smh + B_BASEH + (s & 3) * B_STH;

#pragma unroll
            for (int ks = 0; ks < 2; ++ks) {
                const int col = ks * 16 + tig * 2;
                unsigned af[2][4], bf[8][2];
#pragma unroll
                for (int im = 0; im < 2; ++im) {
                    const __half* base = tA + (m0 + im * 16 + gid) * PADH + col;
                    af[im][0] = *(const unsigned*)(base);
                    af[im][1] = *(const unsigned*)(base + 8 * PADH);
                    af[im][2] = *(const unsigned*)(base + 8);
                    af[im][3] = *(const unsigned*)(base + 8 * PADH + 8);
                }
#pragma unroll
                for (int in = 0; in < 8; ++in) {
                    const __half* bb = tB + (n0 + in * 8 + gid) * PADH + col;
                    bf[in][0] = *(const unsigned*)(bb);
                    bf[in][1] = *(const unsigned*)(bb + 8);
                }
#pragma unroll
                for (int im = 0; im < 2; ++im)
#pragma unroll
                    for (int in = 0; in < 8; ++in)
                        mma_f16(acc[im][in], af[im], bf[in]);
            }
        }

#pragma unroll
        for (int im = 0; im < 2; ++im) {
#pragma unroll
            for (int in = 0; in < 8; ++in) {
                int rr = bm + m0 + im * 16 + gid;
                int cg = n0 + in * 8 + tig * 2;
                float b0 = Wx_b[cg], b1 = Wx_b[cg + 1];
                if (rr < NNODES) {
                    float2 v = make_float2(acc[im][in][0] + b0, acc[im][in][1] + b1);
                    *(float2*)(g_Wx + (size_t)rr * NGEMM + cg) = v;
                }
                int rr2 = rr + 8;
                if (rr2 < NNODES) {
                    float2 v = make_float2(acc[im][in][2] + b0, acc[im][in][3] + b1);
                    *(float2*)(g_Wx + (size_t)rr2 * NGEMM + cg) = v;
                }
            }
        }
        __syncthreads();    // stage reads done before tree staging overwrites smem
    }

    // stage tree weights into smem
    for (int i = tid; i < 4096; i += THREADS) {
        sm[TS_UF + i] = g_Uft[i];
        sm[TS_UI + i] = g_Uit[i];
        sm[TS_UO + i] = g_Uot[i];
        sm[TS_UU + i] = g_Uut[i];
    }
    for (int i = tid; i < 8192; i += THREADS) sm[TS_CV + i] = g_convWt[i];
    gridbar(1);

    // ========== phase 2: leaves ==========
    for (int idx = t0; idx < NLEAF * HID; idx += nt) {
        int node = (NLEAF - 1) + (idx >> 6);
        int o = idx & 63;
        const float* wx = g_Wx + (size_t)node * NGEMM;
        float zi = wx[o]       + g_v[o];
        float zo = wx[128 + o] + g_v[64 + o];
        float zu = wx[192 + o] + g_v[128 + o];
        float c = sigmoidf_(zi) * tanhf(zu);
        g_c[(size_t)node * HID + o] = c;
        g_h[(size_t)node * HID + o] = sigmoidf_(zo) * tanhf(c);
    }
    int bi = 2;
    gridbar(bi++);

    // ========== phase 3: levels d = 12..5, grid-wide ==========
    const int gw = blockIdx.x * TWARPS + warp;
    float* shw = sm + TS_WB + warp * 640;
    float* scw = shw + 256;
    float* saw = shw + 512;
    const float cb0 = conv_b[lane], cb1 = conv_b[lane + 32];

    for (int d = DEPTH - 2; d >= 5; --d) {
        const int n = 1 << d, start = n - 1;
        for (int j = gw * 2; j < n; j += TW * 2) {
            const bool two = (j + 1 < n);
            node_pair(start + j, start + j + (two ? 1 : 0), two, lane,
                      sm + TS_UI, sm + TS_UF, sm + TS_UO, sm + TS_UU, sm + TS_CV,
                      shw, scw, saw, cb0, cb1, out);
        }
        gridbar(bi++);
    }

    // ========== phase 4: levels d = 4..0, block 0 only ==========
    __syncthreads();
    if (blockIdx.x != 0) {
        if (tid == 0) { __threadfence(); atomicAdd(&g_bar[bi], 1u); }
        return;
    }
    if (tid == 0) {
        __threadfence();
        atomicAdd(&g_bar[bi], 1u);
        while (*(volatile unsigned*)&g_bar[bi] < (unsigned)TGRID) { __nanosleep(64); }
        __threadfence();
    }
    __syncthreads();

    for (int d = 4; d >= 0; --d) {
        const int n = 1 << d, start = n - 1;
        for (int j = warp * 2; j < n; j += TWARPS * 2) {
            const bool two = (j + 1 < n);
            node_pair(start + j, start + j + (two ? 1 : 0), two, lane,
                      sm + TS_UI, sm + TS_UF, sm + TS_UO, sm + TS_UU, sm + TS_CV,
                      shw, scw, saw, cb0, cb1, out);
        }
        __syncthreads();
    }

    if (tid < 32) g_bar[tid] = 0;   // reset for graph replay
}

// ---------------- launch ----------------
extern "C" void kernel_launch(void* const* d_in, const int* in_sizes, int n_in,
                              void* d_out, int out_size)
{
    const float* inputs = (const float*)d_in[0];
    const float* Wx_w   = (const float*)d_in[1];
    const float* Wx_b   = (const float*)d_in[2];
    const float* U_i    = (const float*)d_in[3];
    const float* U_f    = (const float*)d_in[4];
    const float* U_o    = (const float*)d_in[5];
    const float* U_u    = (const float*)d_in[6];
    const float* convW  = (const float*)d_in[7];
    const float* conv_b = (const float*)d_in[8];
    float* out = (float*)d_out;

    cudaFuncSetAttribute(mega_kernel, cudaFuncAttributeMaxDynamicSharedMemorySize, SMEM_BYTES);
    mega_kernel<<<TGRID, THREADS, SMEM_BYTES>>>(inputs, Wx_w, Wx_b, U_i, U_f, U_o, U_u,
                                                convW, conv_b, out);
}